// round 4
// baseline (speedup 1.0000x reference)
#include <cuda_runtime.h>
#include <cuda_bf16.h>

#define NN    30000
#define EE    600000
#define IN_C  256
#define HID_C 128
#define OUT_C 64

// ---------------- device scratch (no allocation allowed) ----------------
__device__ int   g_is64;
__device__ int   g_src[EE];
__device__ int   g_dst[EE];
__device__ int   g_deg[NN];
__device__ float g_dinv[NN];
__device__ float g_h1[NN * HID_C];    // X@W1
__device__ float g_agg1[NN * HID_C];  // aggregated layer-1 (then relu'd in place)
__device__ float g_h2[NN * OUT_C];    // relu(h)@W2

// ---------------- edge dtype detection ----------------
// If edge_index is int64 (little-endian, values in [0,30000)), every odd
// 32-bit word is 0. For int32 data those words are random node ids; the
// probability all 128 sampled words are zero is ~(1/30000)^128 ~ 0.
__global__ void detect_dtype_kernel(const unsigned* __restrict__ raw) {
    if (threadIdx.x == 0 && blockIdx.x == 0) {
        int is64 = 1;
        for (int i = 1; i < 256; i += 2) {
            if (raw[i] != 0u) { is64 = 0; break; }
        }
        g_is64 = is64;
    }
}

__global__ void init_deg_kernel() {
    int i = blockIdx.x * blockDim.x + threadIdx.x;
    if (i < NN) g_deg[i] = 1;  // self loop
}

__global__ void prep_edges_kernel(const void* __restrict__ raw) {
    int e = blockIdx.x * blockDim.x + threadIdx.x;
    if (e >= EE) return;
    int s, d;
    if (g_is64) {
        const long long* p = (const long long*)raw;
        s = (int)p[e];
        d = (int)p[EE + e];
    } else {
        const int* p = (const int*)raw;
        s = p[e];
        d = p[EE + e];
    }
    g_src[e] = s;
    g_dst[e] = d;
    atomicAdd(&g_deg[d], 1);
}

__global__ void dinv_kernel() {
    int i = blockIdx.x * blockDim.x + threadIdx.x;
    if (i < NN) g_dinv[i] = 1.0f / sqrtf((float)g_deg[i]);
}

// ---------------- SGEMM with fused self-loop/bias epilogue ----------------
// C = A[M,K] @ B[K,BN].  One block covers the full BN width (HID=128 / OUT=64).
// Epilogue:  H[m,n]   = acc
//            AGG[m,n] = acc * dinv[m]^2 + bias[n]   (self-loop seed + bias)
template<int BN, int TN>
__global__ void __launch_bounds__(256)
sgemm_fused(const float* __restrict__ A, const float* __restrict__ B,
            const float* __restrict__ bias, const float* __restrict__ dinv,
            float* __restrict__ H, float* __restrict__ AGG,
            int M, int K)
{
    constexpr int BM = 128, BK = 8, TM = 8;
    constexpr int TCOLS = BN / TN;          // 16
    __shared__ float As[BK][BM];
    __shared__ float Bs[BK][BN];

    const int tid = threadIdx.x;            // 256 threads
    const int m0  = blockIdx.x * BM;
    const int ty  = tid / TCOLS;            // 0..15
    const int tx  = tid % TCOLS;            // 0..15

    const int a_row = tid >> 1;             // 0..127
    const int a_col = (tid & 1) * 4;        // 0 or 4
    const int b_row = tid / (BN / 4);
    const int b_col = (tid % (BN / 4)) * 4;

    float acc[TM][TN];
#pragma unroll
    for (int i = 0; i < TM; i++)
#pragma unroll
        for (int j = 0; j < TN; j++) acc[i][j] = 0.0f;

    for (int k0 = 0; k0 < K; k0 += BK) {
        int gm = m0 + a_row;
        float4 av = (gm < M) ? *(const float4*)(A + (size_t)gm * K + k0 + a_col)
                             : make_float4(0.f, 0.f, 0.f, 0.f);
        As[a_col + 0][a_row] = av.x;
        As[a_col + 1][a_row] = av.y;
        As[a_col + 2][a_row] = av.z;
        As[a_col + 3][a_row] = av.w;

        if (BN == 128 || tid < (BK * BN) / 4) {
            float4 bv = *(const float4*)(B + (size_t)(k0 + b_row) * BN + b_col);
            *(float4*)&Bs[b_row][b_col] = bv;
        }
        __syncthreads();

#pragma unroll
        for (int k = 0; k < BK; k++) {
            float ra[TM], rb[TN];
#pragma unroll
            for (int i = 0; i < TM; i++) ra[i] = As[k][ty * TM + i];
#pragma unroll
            for (int j = 0; j < TN; j++) rb[j] = Bs[k][tx * TN + j];
#pragma unroll
            for (int i = 0; i < TM; i++)
#pragma unroll
                for (int j = 0; j < TN; j++) acc[i][j] += ra[i] * rb[j];
        }
        __syncthreads();
    }

#pragma unroll
    for (int i = 0; i < TM; i++) {
        int gm = m0 + ty * TM + i;
        if (gm >= M) continue;
        float dv  = dinv[gm];
        float dv2 = dv * dv;
#pragma unroll
        for (int j = 0; j < TN; j += 4) {
            int gn = tx * TN + j;
            float4 hv = make_float4(acc[i][j], acc[i][j + 1], acc[i][j + 2], acc[i][j + 3]);
            *(float4*)(H + (size_t)gm * BN + gn) = hv;
            float4 ag;
            ag.x = hv.x * dv2 + bias[gn + 0];
            ag.y = hv.y * dv2 + bias[gn + 1];
            ag.z = hv.z * dv2 + bias[gn + 2];
            ag.w = hv.w * dv2 + bias[gn + 3];
            *(float4*)(AGG + (size_t)gm * BN + gn) = ag;
        }
    }
}

// ---------------- edge scatter: out[dst] += h[src] * dinv[s]*dinv[d] ----------------
// F4 = feature_width/4 threads per edge, each handles one float4 and issues a
// single vector atomicAdd (RED.128 on sm_90+).
template<int F4>
__global__ void scatter_kernel(const float4* __restrict__ h, float* __restrict__ out) {
    unsigned t = blockIdx.x * blockDim.x + threadIdx.x;
    unsigned e = t / F4;
    unsigned j = t % F4;
    if (e >= EE) return;
    int s = g_src[e];
    int d = g_dst[e];
    float nrm = __ldg(&g_dinv[s]) * __ldg(&g_dinv[d]);
    float4 v = __ldg(&h[(size_t)s * F4 + j]);
    float4 m = make_float4(v.x * nrm, v.y * nrm, v.z * nrm, v.w * nrm);
    atomicAdd((float4*)(out + (size_t)d * (F4 * 4) + 4 * j), m);
}

__global__ void relu_kernel(float* __restrict__ a, int n) {
    int i = blockIdx.x * blockDim.x + threadIdx.x;
    if (i < n) a[i] = fmaxf(a[i], 0.0f);
}

// ---------------- launch ----------------
extern "C" void kernel_launch(void* const* d_in, const int* in_sizes, int n_in,
                              void* d_out, int out_size) {
    const float* x  = (const float*)d_in[0];
    const void*  ei = d_in[1];
    const float* W1 = (const float*)d_in[2];
    const float* b1 = (const float*)d_in[3];
    const float* W2 = (const float*)d_in[4];
    const float* b2 = (const float*)d_in[5];
    float* out = (float*)d_out;

    float *p_h1, *p_agg1, *p_h2, *p_dinv;
    cudaGetSymbolAddress((void**)&p_h1,   g_h1);
    cudaGetSymbolAddress((void**)&p_agg1, g_agg1);
    cudaGetSymbolAddress((void**)&p_h2,   g_h2);
    cudaGetSymbolAddress((void**)&p_dinv, g_dinv);

    detect_dtype_kernel<<<1, 1>>>((const unsigned*)ei);
    init_deg_kernel<<<(NN + 255) / 256, 256>>>();
    prep_edges_kernel<<<(EE + 255) / 256, 256>>>(ei);
    dinv_kernel<<<(NN + 255) / 256, 256>>>();

    // Layer 1: h1 = x@W1 ; agg1 = h1*dinv^2 + b1 ; scatter ; relu
    sgemm_fused<HID_C, 8><<<(NN + 127) / 128, 256>>>(x, W1, b1, p_dinv, p_h1, p_agg1, NN, IN_C);
    scatter_kernel<HID_C / 4><<<(EE * (HID_C / 4) + 255) / 256, 256>>>((const float4*)p_h1, p_agg1);
    relu_kernel<<<(NN * HID_C + 255) / 256, 256>>>(p_agg1, NN * HID_C);

    // Layer 2: h2 = relu(h)@W2 ; out = h2*dinv^2 + b2 ; scatter into out
    sgemm_fused<OUT_C, 4><<<(NN + 127) / 128, 256>>>(p_agg1, W2, b2, p_dinv, p_h2, out, NN, HID_C);
    scatter_kernel<OUT_C / 4><<<(EE * (OUT_C / 4) + 255) / 256, 256>>>((const float4*)p_h2, out);
}

// round 5
// speedup vs baseline: 1.0264x; 1.0264x over previous
#include <cuda_runtime.h>
#include <cuda_bf16.h>

#define NN    30000
#define EE    600000
#define IN_C  256
#define HID_C 128
#define OUT_C 64

// ---------------- device scratch (no allocation allowed) ----------------
__device__ int   g_src[EE];
__device__ int   g_dst[EE];
__device__ int   g_deg[NN];      // edge indegree (self-loop NOT included)
__device__ float g_dinv[NN];     // 1/sqrt(indeg+1)
__device__ int   g_ptr[NN + 1];  // CSR row pointers (by dst)
__device__ int   g_cur[NN];      // atomic fill cursors
__device__ int2  g_csr[EE];      // (src, norm bits) sorted by dst
__device__ float g_h1[NN * HID_C];    // X@W1
__device__ float g_agg1[NN * HID_C];  // relu(aggregate(h1))
__device__ float g_h2[NN * OUT_C];    // agg1@W2

// ---------------- prep ----------------
__global__ void zero_deg_kernel() {
    int i = blockIdx.x * blockDim.x + threadIdx.x;
    if (i < NN) g_deg[i] = 0;
}

// Decode edges (runtime int64/int32 detection per block: for little-endian
// int64 node ids < 30000 every odd 32-bit word is 0) and count indegree.
__global__ void prep_edges_kernel(const unsigned* __restrict__ raw) {
    __shared__ int s_is64;
    if (threadIdx.x == 0) {
        int is64 = 1;
        for (int i = 1; i < 64; i += 2)
            if (raw[i] != 0u) { is64 = 0; break; }
        s_is64 = is64;
    }
    __syncthreads();
    int e = blockIdx.x * blockDim.x + threadIdx.x;
    if (e >= EE) return;
    int s, d;
    if (s_is64) {
        const long long* p = (const long long*)raw;
        s = (int)p[e];
        d = (int)p[EE + e];
    } else {
        const int* p = (const int*)raw;
        s = p[e];
        d = p[EE + e];
    }
    g_src[e] = s;
    g_dst[e] = d;
    atomicAdd(&g_deg[d], 1);
}

// Single-block exclusive scan of indegree -> CSR pointers + cursors.
__global__ void __launch_bounds__(1024) scan_kernel() {
    __shared__ int sh[1024];
    __shared__ int s_carry;
    int tid = threadIdx.x;
    if (tid == 0) s_carry = 0;
    __syncthreads();
    for (int base = 0; base < NN; base += 1024) {
        int i = base + tid;
        int v = (i < NN) ? g_deg[i] : 0;
        sh[tid] = v;
        __syncthreads();
#pragma unroll
        for (int off = 1; off < 1024; off <<= 1) {
            int t = (tid >= off) ? sh[tid - off] : 0;
            __syncthreads();
            sh[tid] += t;
            __syncthreads();
        }
        int excl = s_carry + sh[tid] - v;
        if (i < NN) { g_ptr[i] = excl; g_cur[i] = excl; }
        int total = sh[1023];
        __syncthreads();
        if (tid == 0) s_carry += total;
        __syncthreads();
    }
    if (tid == 0) g_ptr[NN] = s_carry;   // == EE
}

__global__ void dinv_kernel() {
    int i = blockIdx.x * blockDim.x + threadIdx.x;
    if (i < NN) g_dinv[i] = rsqrtf((float)(g_deg[i] + 1));
}

__global__ void fill_csr_kernel() {
    int e = blockIdx.x * blockDim.x + threadIdx.x;
    if (e >= EE) return;
    int s = g_src[e];
    int d = g_dst[e];
    int slot = atomicAdd(&g_cur[d], 1);
    float nrm = g_dinv[s] * g_dinv[d];
    g_csr[slot] = make_int2(s, __float_as_int(nrm));
}

// ---------------- SGEMM: C = A[M,K] @ B[K,BN], full width per block ----------------
template<int BN, int TN>
__global__ void __launch_bounds__(256)
sgemm(const float* __restrict__ A, const float* __restrict__ B,
      float* __restrict__ C, int M, int K)
{
    constexpr int BM = 128, BK = 8, TM = 8;
    constexpr int TCOLS = BN / TN;          // 16
    __shared__ float As[BK][BM];
    __shared__ float Bs[BK][BN];

    const int tid = threadIdx.x;
    const int m0  = blockIdx.x * BM;
    const int ty  = tid / TCOLS;
    const int tx  = tid % TCOLS;

    const int a_row = tid >> 1;
    const int a_col = (tid & 1) * 4;
    const int b_row = tid / (BN / 4);
    const int b_col = (tid % (BN / 4)) * 4;

    float acc[TM][TN];
#pragma unroll
    for (int i = 0; i < TM; i++)
#pragma unroll
        for (int j = 0; j < TN; j++) acc[i][j] = 0.0f;

    for (int k0 = 0; k0 < K; k0 += BK) {
        int gm = m0 + a_row;
        float4 av = (gm < M) ? *(const float4*)(A + (size_t)gm * K + k0 + a_col)
                             : make_float4(0.f, 0.f, 0.f, 0.f);
        As[a_col + 0][a_row] = av.x;
        As[a_col + 1][a_row] = av.y;
        As[a_col + 2][a_row] = av.z;
        As[a_col + 3][a_row] = av.w;

        if (BN == 128 || tid < (BK * BN) / 4) {
            float4 bv = *(const float4*)(B + (size_t)(k0 + b_row) * BN + b_col);
            *(float4*)&Bs[b_row][b_col] = bv;
        }
        __syncthreads();

#pragma unroll
        for (int k = 0; k < BK; k++) {
            float ra[TM], rb[TN];
#pragma unroll
            for (int i = 0; i < TM; i++) ra[i] = As[k][ty * TM + i];
#pragma unroll
            for (int j = 0; j < TN; j++) rb[j] = Bs[k][tx * TN + j];
#pragma unroll
            for (int i = 0; i < TM; i++)
#pragma unroll
                for (int j = 0; j < TN; j++) acc[i][j] += ra[i] * rb[j];
        }
        __syncthreads();
    }

#pragma unroll
    for (int i = 0; i < TM; i++) {
        int gm = m0 + ty * TM + i;
        if (gm >= M) continue;
#pragma unroll
        for (int j = 0; j < TN; j += 4) {
            int gn = tx * TN + j;
            *(float4*)(C + (size_t)gm * BN + gn) =
                make_float4(acc[i][j], acc[i][j + 1], acc[i][j + 2], acc[i][j + 3]);
        }
    }
}

// ---------------- CSR pull-aggregation, layer 1 (F=128) ----------------
// One warp per node; lane owns one float4 (4 features). Self-loop + bias +
// relu fused. out = relu(b + h[n]*dinv[n]^2 + sum_e h[src]*norm).
__global__ void __launch_bounds__(256)
agg1_kernel(const float4* __restrict__ h, const float* __restrict__ bias,
            float4* __restrict__ out)
{
    int warp = threadIdx.x >> 5;
    int lane = threadIdx.x & 31;
    int node = blockIdx.x * 8 + warp;          // grid = 3750, exact

    float dv  = g_dinv[node];
    float dv2 = dv * dv;
    float4 b  = ((const float4*)bias)[lane];
    float4 sv = h[(size_t)node * 32 + lane];
    float4 acc = make_float4(b.x + sv.x * dv2, b.y + sv.y * dv2,
                             b.z + sv.z * dv2, b.w + sv.w * dv2);

    int beg = g_ptr[node], end = g_ptr[node + 1];
    for (int k = beg; k < end; k += 32) {
        int idx = k + lane;
        int2 pr = (idx < end) ? g_csr[idx] : make_int2(0, 0);
        int cnt = min(32, end - k);
        for (int i = 0; i < cnt; i++) {
            int   ss = __shfl_sync(0xffffffffu, pr.x, i);
            float nn = __int_as_float(__shfl_sync(0xffffffffu, pr.y, i));
            float4 v = h[(size_t)ss * 32 + lane];
            acc.x += v.x * nn; acc.y += v.y * nn;
            acc.z += v.z * nn; acc.w += v.w * nn;
        }
    }
    out[(size_t)node * 32 + lane] =
        make_float4(fmaxf(acc.x, 0.f), fmaxf(acc.y, 0.f),
                    fmaxf(acc.z, 0.f), fmaxf(acc.w, 0.f));
}

// ---------------- CSR pull-aggregation, layer 2 (F=64) ----------------
// 16-lane sub-warp per node; lane owns one float4. Writes d_out directly.
__global__ void __launch_bounds__(256)
agg2_kernel(const float4* __restrict__ h, const float* __restrict__ bias,
            float4* __restrict__ out)
{
    int sub  = threadIdx.x & 15;
    int node = blockIdx.x * 16 + (threadIdx.x >> 4);   // grid = 1875, exact

    float dv  = g_dinv[node];
    float dv2 = dv * dv;
    float4 b  = ((const float4*)bias)[sub];
    float4 sv = h[(size_t)node * 16 + sub];
    float4 acc = make_float4(b.x + sv.x * dv2, b.y + sv.y * dv2,
                             b.z + sv.z * dv2, b.w + sv.w * dv2);

    int beg = g_ptr[node], end = g_ptr[node + 1];
    for (int k = beg; k < end; k += 16) {
        int idx = k + sub;
        int2 pr = (idx < end) ? g_csr[idx] : make_int2(0, 0);
        int cnt = min(16, end - k);
        for (int i = 0; i < cnt; i++) {
            int   ss = __shfl_sync(0xffffffffu, pr.x, i, 16);
            float nn = __int_as_float(__shfl_sync(0xffffffffu, pr.y, i, 16));
            float4 v = h[(size_t)ss * 16 + sub];
            acc.x += v.x * nn; acc.y += v.y * nn;
            acc.z += v.z * nn; acc.w += v.w * nn;
        }
    }
    out[(size_t)node * 16 + sub] = acc;
}

// ---------------- launch ----------------
extern "C" void kernel_launch(void* const* d_in, const int* in_sizes, int n_in,
                              void* d_out, int out_size) {
    const float* x  = (const float*)d_in[0];
    const void*  ei = d_in[1];
    const float* W1 = (const float*)d_in[2];
    const float* b1 = (const float*)d_in[3];
    const float* W2 = (const float*)d_in[4];
    const float* b2 = (const float*)d_in[5];
    float* out = (float*)d_out;

    float *p_h1, *p_agg1, *p_h2;
    cudaGetSymbolAddress((void**)&p_h1,   g_h1);
    cudaGetSymbolAddress((void**)&p_agg1, g_agg1);
    cudaGetSymbolAddress((void**)&p_h2,   g_h2);

    zero_deg_kernel<<<(NN + 255) / 256, 256>>>();                 // 1
    prep_edges_kernel<<<(EE + 255) / 256, 256>>>((const unsigned*)ei); // 2
    scan_kernel<<<1, 1024>>>();                                   // 3
    dinv_kernel<<<(NN + 255) / 256, 256>>>();                     // 4
    fill_csr_kernel<<<(EE + 255) / 256, 256>>>();                 // 5

    // Layer 1                                                    // 6 = ncu target
    sgemm<HID_C, 8><<<(NN + 127) / 128, 256>>>(x, W1, p_h1, NN, IN_C);
    agg1_kernel<<<NN / 8, 256>>>((const float4*)p_h1, b1, (float4*)p_agg1);   // 7

    // Layer 2
    sgemm<OUT_C, 4><<<(NN + 127) / 128, 256>>>(p_agg1, W2, p_h2, NN, HID_C);  // 8
    agg2_kernel<<<NN / 16, 256>>>((const float4*)p_h2, b2, (float4*)out);     // 9
}